// round 3
// baseline (speedup 1.0000x reference)
#include <cuda_runtime.h>
#include <cstdint>

#define THREADS 256
#define MDIM 1024
#define CDIM 128
#define MIDD 64
#define TROWS 64
#define NTILES (MDIM / TROWS)
#define KSTRIDE 33                      /* float4 per ip row (66 u64 / 2) */
#define KBUF_F4 (64 * KSTRIDE)          /* 2112 float4 per k buffer */

// shared memory layout (float offsets)
#define OFF_K 0
#define SZ_K (2 * KBUF_F4 * 4)          /* 16896 floats : double-buffered k tiles */
#define OFF_QW SZ_K                     /* 16896 : wq [ip][32 float4], XOR-slotted */
#define SZ_QW (64 * 32 * 4)             /* 8192 floats */
#define OFF_LG (OFF_QW + SZ_QW)         /* 25088 : logits / alphas */
#define OFF_POOL (OFF_LG + MDIM)        /* 26112 */
#define OFF_RED (OFF_POOL + MIDD)       /* 26176 */
#define OFF_BW (OFF_RED + 32)           /* 26208 : bb(64) + wl(64) */
#define SMEM_FLOATS (OFF_BW + 128)      /* 26336 */
#define SMEM_BYTES (SMEM_FLOATS * 4)    /* 105344 B -> 2 CTAs/SM */

typedef unsigned long long u64;

__device__ __forceinline__ u64 ffma2(u64 a, u64 b, u64 c) {
    u64 d;
    asm("fma.rn.f32x2 %0, %1, %2, %3;" : "=l"(d) : "l"(a), "l"(b), "l"(c));
    return d;
}
__device__ __forceinline__ u64 pack2(float lo, float hi) {
    u64 d;
    asm("mov.b64 %0, {%1, %2};" : "=l"(d) : "f"(lo), "f"(hi));
    return d;
}
__device__ __forceinline__ float f2lo(u64 v) { return __uint_as_float((unsigned)v); }
__device__ __forceinline__ float f2hi(u64 v) { return __uint_as_float((unsigned)(v >> 32)); }

__device__ __forceinline__ void cpa8(uint32_t dst, const float* src) {
    asm volatile("cp.async.ca.shared.global [%0], [%1], 8;" :: "r"(dst), "l"(src) : "memory");
}

__global__ void __launch_bounds__(THREADS, 2) scatt_kernel(
    const float* __restrict__ q, const float* __restrict__ kf,
    const int* __restrict__ msk, const float* __restrict__ v1,
    const float* __restrict__ v2g, const float* __restrict__ wb,
    const float* __restrict__ bb, const float* __restrict__ wl,
    const float* __restrict__ bl, const float* __restrict__ wl2,
    const float* __restrict__ bl2, float* __restrict__ out)
{
    extern __shared__ float sm[];
    float* slg   = sm + OFF_LG;
    float* spool = sm + OFF_POOL;
    float* sred  = sm + OFF_RED;
    float* sbw   = sm + OFF_BW;

    const int tid = threadIdx.x;
    const int bh = blockIdx.x;
    const int b = bh >> 3;
    const int h = bh & 7;

    const float* qv  = q   + bh * CDIM;
    const float* kfp = kf  + (size_t)bh * MDIM * CDIM;
    const float* v2p = v2g + (size_t)bh * MDIM * CDIM;
    const float* wbh = wb  + h * CDIM * MIDD;
    const int*   mkp = msk + b * MDIM;

    const uint32_t smbase = (uint32_t)__cvta_generic_to_shared(sm);

    if (tid == 0) sred[0] = 0.f;
    __syncthreads();

    // ---- kick off fill of tile 0 into buffer 0 ----
    #pragma unroll
    for (int it = 0; it < 16; ++it) {
        int idx = tid + it * THREADS;
        int ip = idx & 63, mr = idx >> 6;
        cpa8(smbase + (uint32_t)((ip * 66 + mr) * 8),
             kfp + (size_t)mr * CDIM + 2 * ip);
    }
    asm volatile("cp.async.commit_group;" ::: "memory");

    // ---- build wq: word(ip,o) = (q[2ip]*W[2ip][o], q[2ip+1]*W[2ip+1][o]) ----
    // stored at u64 addr (ip*32 + og*4 + (u ^ (og>>1)))*2 + (o&1),
    // og=o>>3, u=(o>>1)&3  -> reader slot permutation makes reads conflict-free.
    {
        float2* wq2 = (float2*)(sm + OFF_QW);
        for (int widx = tid; widx < 64 * MIDD; widx += THREADS) {
            int o = widx & 63, ip = widx >> 6, i = ip << 1;
            float a0 = qv[i]     * wbh[i * MIDD + o];
            float a1 = qv[i + 1] * wbh[(i + 1) * MIDD + o];
            int og = o >> 3, u = (o >> 1) & 3, slot = u ^ (og >> 1);
            wq2[(ip * 32 + og * 4 + slot) * 2 + (o & 1)] = make_float2(a0, a1);
        }
    }
    // ---- mask count (exact: integer-valued) ----
    {
        float cl = 0.f;
        for (int m = tid; m < MDIM; m += THREADS) cl += (float)mkp[m];
        #pragma unroll
        for (int off = 16; off; off >>= 1) cl += __shfl_xor_sync(0xffffffffu, cl, off);
        if ((tid & 31) == 0) atomicAdd(&sred[0], cl);
    }
    if (tid < MIDD) { sbw[tid] = bb[h * MIDD + tid]; sbw[MIDD + tid] = wl[h * MIDD + tid]; }

    const int og = tid & 7;    // 8 o-groups, thread owns o = og*8 .. og*8+7
    const int mg = tid >> 3;   // 32 m-groups x 2 rows
    const int c = og >> 1;     // slot permutation key
    const float blv = bl[h];

    u64 acc[2][8];
    #pragma unroll
    for (int r = 0; r < 2; ++r)
        #pragma unroll
        for (int j = 0; j < 8; ++j) acc[r][j] = 0ull;
    float pacc[8] = {0.f,0.f,0.f,0.f,0.f,0.f,0.f,0.f};

    const float4* wp0 = (const float4*)(sm + OFF_QW) + og * 4 + (0 ^ c);
    const float4* wp1 = (const float4*)(sm + OFF_QW) + og * 4 + (1 ^ c);
    const float4* wp2 = (const float4*)(sm + OFF_QW) + og * 4 + (2 ^ c);
    const float4* wp3 = (const float4*)(sm + OFF_QW) + og * 4 + (3 ^ c);

    for (int t = 0; t < NTILES; ++t) {
        // prefetch next tile into the other buffer
        if (t + 1 < NTILES) {
            const int m0n = (t + 1) * TROWS;
            const uint32_t kdst = smbase + (uint32_t)(((t + 1) & 1) * KBUF_F4 * 16);
            #pragma unroll
            for (int it = 0; it < 16; ++it) {
                int idx = tid + it * THREADS;
                int ip = idx & 63, mr = idx >> 6;
                cpa8(kdst + (uint32_t)((ip * 66 + mr) * 8),
                     kfp + (size_t)(m0n + mr) * CDIM + 2 * ip);
            }
            asm volatile("cp.async.commit_group;" ::: "memory");
            asm volatile("cp.async.wait_group 1;" ::: "memory");
        } else {
            asm volatile("cp.async.wait_group 0;" ::: "memory");
        }
        __syncthreads();

        const float4* kp = (const float4*)sm + (t & 1) * KBUF_F4 + mg;

        #pragma unroll 8
        for (int ip = 0; ip < 64; ++ip) {
            float4 kk = kp[ip * KSTRIDE];
            u64 k0 = pack2(kk.x, kk.y);   // row mg*2   : (k[m][2ip], k[m][2ip+1])
            u64 k1 = pack2(kk.z, kk.w);   // row mg*2+1
            float4 w;
            w = wp0[ip * 32];
            { u64 w0 = pack2(w.x, w.y), w1 = pack2(w.z, w.w);
              acc[0][0] = ffma2(k0, w0, acc[0][0]); acc[0][1] = ffma2(k0, w1, acc[0][1]);
              acc[1][0] = ffma2(k1, w0, acc[1][0]); acc[1][1] = ffma2(k1, w1, acc[1][1]); }
            w = wp1[ip * 32];
            { u64 w0 = pack2(w.x, w.y), w1 = pack2(w.z, w.w);
              acc[0][2] = ffma2(k0, w0, acc[0][2]); acc[0][3] = ffma2(k0, w1, acc[0][3]);
              acc[1][2] = ffma2(k1, w0, acc[1][2]); acc[1][3] = ffma2(k1, w1, acc[1][3]); }
            w = wp2[ip * 32];
            { u64 w0 = pack2(w.x, w.y), w1 = pack2(w.z, w.w);
              acc[0][4] = ffma2(k0, w0, acc[0][4]); acc[0][5] = ffma2(k0, w1, acc[0][5]);
              acc[1][4] = ffma2(k1, w0, acc[1][4]); acc[1][5] = ffma2(k1, w1, acc[1][5]); }
            w = wp3[ip * 32];
            { u64 w0 = pack2(w.x, w.y), w1 = pack2(w.z, w.w);
              acc[0][6] = ffma2(k0, w0, acc[0][6]); acc[0][7] = ffma2(k0, w1, acc[0][7]);
              acc[1][6] = ffma2(k1, w0, acc[1][6]); acc[1][7] = ffma2(k1, w1, acc[1][7]); }
        }

        // epilogue: bias + relu + pool partials + logit projection
        const int m0 = t * TROWS;
        #pragma unroll
        for (int r = 0; r < 2; ++r) {
            int m = m0 + mg * 2 + r;
            float mk = (float)mkp[m];
            float ls = 0.f;
            #pragma unroll
            for (int j = 0; j < 8; ++j) {
                int o = og * 8 + j;               // acc[r][j] <-> o = og*8 + 2s + half, j=2s+half
                float a = f2lo(acc[r][j]) + f2hi(acc[r][j]) + sbw[o];
                a = fmaxf(a, 0.f);
                pacc[j] = fmaf(a, mk, pacc[j]);
                ls = fmaf(a, sbw[MIDD + o], ls);
                acc[r][j] = 0ull;
            }
            ls += __shfl_down_sync(0xffffffffu, ls, 4, 8);
            ls += __shfl_down_sync(0xffffffffu, ls, 2, 8);
            ls += __shfl_down_sync(0xffffffffu, ls, 1, 8);
            if (og == 0) slg[m] = (mk == 0.f) ? -1e9f : (ls + blv);
        }
        __syncthreads();
    }

    // ---- pool reduction over mg : stage [32][64] in k region ----
    #pragma unroll
    for (int j = 0; j < 8; ++j) sm[mg * 64 + og * 8 + j] = pacc[j];
    __syncthreads();
    if (tid < MIDD) {
        float s = 0.f;
        #pragma unroll
        for (int k = 0; k < 32; ++k) s += sm[k * 64 + tid];
        spool[tid] = s;
    }
    __syncthreads();

    // ---- softmax over slg ----
    float lm = -3.0e38f;
    for (int m = tid; m < MDIM; m += THREADS) lm = fmaxf(lm, slg[m]);
    #pragma unroll
    for (int off = 16; off; off >>= 1) lm = fmaxf(lm, __shfl_xor_sync(0xffffffffu, lm, off));
    if ((tid & 31) == 0) sred[1 + (tid >> 5)] = lm;
    __syncthreads();
    if (tid == 0) {
        float g = sred[1];
        #pragma unroll
        for (int w = 1; w < 8; ++w) g = fmaxf(g, sred[1 + w]);
        sred[9] = g;
    }
    __syncthreads();
    const float gmax = sred[9];
    float es = 0.f;
    for (int m = tid; m < MDIM; m += THREADS) {
        float e = expf(slg[m] - gmax);
        slg[m] = e;
        es += e;
    }
    #pragma unroll
    for (int off = 16; off; off >>= 1) es += __shfl_xor_sync(0xffffffffu, es, off);
    if ((tid & 31) == 0) sred[10 + (tid >> 5)] = es;
    __syncthreads();
    if (tid == 0) {
        float s = 0.f;
        #pragma unroll
        for (int w = 0; w < 8; ++w) s += sred[10 + w];
        sred[18] = 1.f / s;
    }
    __syncthreads();
    const float inv = sred[18];
    for (int m = tid; m < MDIM; m += THREADS) slg[m] *= inv;
    __syncthreads();

    // ---- v2 = sum_m alpha[m] * value2[m,:]  (8 m-segments x 32 float4 ch) ----
    {
        const int cb = (tid & 31) << 2;
        const int seg = tid >> 5;
        const float* vp = v2p + cb;
        float4 va = make_float4(0.f, 0.f, 0.f, 0.f);
        #pragma unroll 4
        for (int m = seg * 128; m < seg * 128 + 128; ++m) {
            float al = slg[m];
            float4 x = *(const float4*)(vp + (size_t)m * CDIM);
            va.x = fmaf(al, x.x, va.x);
            va.y = fmaf(al, x.y, va.y);
            va.z = fmaf(al, x.z, va.z);
            va.w = fmaf(al, x.w, va.w);
        }
        sm[seg * 128 + cb + 0] = va.x;
        sm[seg * 128 + cb + 1] = va.y;
        sm[seg * 128 + cb + 2] = va.z;
        sm[seg * 128 + cb + 3] = va.w;
    }
    __syncthreads();

    // ---- alpha_channel + final output ----
    if (tid < CDIM) {
        const int ch = tid;
        float v2c = 0.f;
        #pragma unroll
        for (int k = 0; k < 8; ++k) v2c += sm[k * 128 + ch];
        const float invc = 1.f / sred[0];
        float x = bl2[h * CDIM + ch];
        const float* w2 = wl2 + h * MIDD * CDIM + ch;
        #pragma unroll 8
        for (int o = 0; o < MIDD; ++o) x = fmaf(spool[o] * invc, w2[o * CDIM], x);
        float sig = 1.f / (1.f + expf(-x));
        out[bh * CDIM + ch] = v1[bh * CDIM + ch] * v2c * sig;
    }
}

extern "C" void kernel_launch(void* const* d_in, const int* in_sizes, int n_in,
                              void* d_out, int out_size) {
    const float* q   = (const float*)d_in[0];
    const float* kf  = (const float*)d_in[1];
    const int*   msk = (const int*)d_in[2];
    const float* v1  = (const float*)d_in[3];
    const float* v2  = (const float*)d_in[4];
    const float* wb  = (const float*)d_in[5];
    const float* bbp = (const float*)d_in[6];
    const float* wlp = (const float*)d_in[7];
    const float* blp = (const float*)d_in[8];
    const float* wl2 = (const float*)d_in[9];
    const float* bl2 = (const float*)d_in[10];
    float* out = (float*)d_out;

    cudaFuncSetAttribute(scatt_kernel, cudaFuncAttributeMaxDynamicSharedMemorySize, SMEM_BYTES);
    scatt_kernel<<<512, THREADS, SMEM_BYTES>>>(q, kf, msk, v1, v2, wb, bbp, wlp, blp, wl2, bl2, out);
}

// round 5
// speedup vs baseline: 2.1155x; 2.1155x over previous
#include <cuda_runtime.h>
#include <cuda_bf16.h>
#include <cstdint>

#define THREADS 512
#define MDIM 1024
#define CDIM 128
#define MIDD 64
#define TM 128
#define NTILES 8
#define SA 272                      /* row stride bytes (136 bf16) for A and B tiles */

// ---- smem byte offsets ----
#define A_HI0   0
#define A_HI1   34816
#define A_LO0   69632
#define A_LO1   104448
#define B_HI    139264
#define B_LO    156672
#define SMASK   174080              /* 1024 floats */
#define SLG     178176              /* 1024 floats */
#define SLGP    182272              /* 128 x 2 floats */
#define PSTAGE  183296              /* 16 x 32 floats */
#define SPOOL   185344              /* 64 floats */
#define SBB     185600
#define SWL     185856
#define SRED    186112              /* 64 floats */
#define SMEM_TOTAL 186624

__device__ __forceinline__ uint32_t smem_u32(const void* p) {
    uint32_t a;
    asm("{ .reg .u64 t; cvta.to.shared.u64 t, %1; cvt.u32.u64 %0, t; }" : "=r"(a) : "l"(p));
    return a;
}
#define LDSM4(r0, r1, r2, r3, addr) \
    asm volatile("ldmatrix.sync.aligned.m8n8.x4.shared.b16 {%0,%1,%2,%3}, [%4];" \
                 : "=r"(r0), "=r"(r1), "=r"(r2), "=r"(r3) : "r"(addr))

__device__ __forceinline__ void mma16816(float* d, uint32_t a0, uint32_t a1, uint32_t a2, uint32_t a3,
                                         uint32_t b0, uint32_t b1) {
    asm volatile("mma.sync.aligned.m16n8k16.row.col.f32.bf16.bf16.f32 "
                 "{%0,%1,%2,%3}, {%4,%5,%6,%7}, {%8,%9}, {%0,%1,%2,%3};"
                 : "+f"(d[0]), "+f"(d[1]), "+f"(d[2]), "+f"(d[3])
                 : "r"(a0), "r"(a1), "r"(a2), "r"(a3), "r"(b0), "r"(b1));
}

__device__ __forceinline__ void cvt_hilo(float4 v, uint2& hi, uint2& lo) {
    __nv_bfloat162 h01 = __floats2bfloat162_rn(v.x, v.y);
    __nv_bfloat162 h23 = __floats2bfloat162_rn(v.z, v.w);
    float r0 = v.x - __bfloat162float(h01.x);
    float r1 = v.y - __bfloat162float(h01.y);
    float r2 = v.z - __bfloat162float(h23.x);
    float r3 = v.w - __bfloat162float(h23.y);
    __nv_bfloat162 l01 = __floats2bfloat162_rn(r0, r1);
    __nv_bfloat162 l23 = __floats2bfloat162_rn(r2, r3);
    hi = make_uint2(*(uint32_t*)&h01, *(uint32_t*)&h23);
    lo = make_uint2(*(uint32_t*)&l01, *(uint32_t*)&l23);
}

__global__ void __launch_bounds__(THREADS, 1) scatt_hmma(
    const float* __restrict__ q, const float* __restrict__ kf,
    const int* __restrict__ msk, const float* __restrict__ v1,
    const float* __restrict__ v2g, const float* __restrict__ wb,
    const float* __restrict__ bb, const float* __restrict__ wl,
    const float* __restrict__ bl, const float* __restrict__ wl2,
    const float* __restrict__ bl2, float* __restrict__ out)
{
    extern __shared__ char smem[];
    float* smask = (float*)(smem + SMASK);
    float* slg   = (float*)(smem + SLG);
    float* slgp  = (float*)(smem + SLGP);
    float* ps    = (float*)(smem + PSTAGE);
    float* spool = (float*)(smem + SPOOL);
    float* sbb   = (float*)(smem + SBB);
    float* swl   = (float*)(smem + SWL);
    float* sred  = (float*)(smem + SRED);

    const int tid = threadIdx.x;
    const int wid = tid >> 5;
    const int lane = tid & 31;
    const int bh = blockIdx.x;
    const int b = bh >> 3;
    const int h = bh & 7;

    const float* qv  = q   + bh * CDIM;
    const float* kfp = kf  + (size_t)bh * MDIM * CDIM;
    const float* v2p = v2g + (size_t)bh * MDIM * CDIM;
    const float* wbh = wb  + h * CDIM * MIDD;
    const int*   mkp = msk + b * MDIM;

    const uint32_t smb = smem_u32(smem);

    // ---- build B hi/lo: qw[o][i] = q[i]*W[i][o], row=o (n), col=i (k), stride SA ----
    for (int idx = tid; idx < CDIM * MIDD; idx += THREADS) {
        int i = idx >> 6, o = idx & 63;
        float w = qv[i] * wbh[idx];
        __nv_bfloat16 hi = __float2bfloat16(w);
        __nv_bfloat16 lo = __float2bfloat16(w - __bfloat162float(hi));
        uint32_t off = (uint32_t)(o * SA + i * 2);
        *(__nv_bfloat16*)(smem + B_HI + off) = hi;
        *(__nv_bfloat16*)(smem + B_LO + off) = lo;
    }
    // ---- mask to smem + exact count (warp partials) ----
    {
        float cl = 0.f;
        for (int m = tid; m < MDIM; m += THREADS) {
            float mv = (float)mkp[m];
            smask[m] = mv;
            cl += mv;
        }
        #pragma unroll
        for (int off = 16; off; off >>= 1) cl += __shfl_xor_sync(0xffffffffu, cl, off);
        if (lane == 0) sred[1 + wid] = cl;
    }
    if (tid < MIDD) { sbb[tid] = bb[h * MIDD + tid]; swl[tid] = wl[h * MIDD + tid]; }

    // ---- preload tile 0 (convert + STS into buf 0) ----
    {
        #pragma unroll
        for (int it = 0; it < 8; ++it) {
            int idx = tid + it * THREADS;
            int row = idx >> 5, c4 = idx & 31;
            float4 v = *(const float4*)(kfp + (size_t)row * CDIM + c4 * 4);
            uint2 hi, lo;
            cvt_hilo(v, hi, lo);
            uint32_t off = (uint32_t)(row * SA + c4 * 8);
            *(uint2*)(smem + A_HI0 + off) = hi;
            *(uint2*)(smem + A_LO0 + off) = lo;
        }
    }
    __syncthreads();

    // ---- warp tiling: rb = wid&7 (rows rb*16..+16), chh = wid>>3 (cols chh*32..+32) ----
    const int rb = wid & 7;
    const int chh = wid >> 3;
    const int seg = lane >> 3;
    const int lr = lane & 7;
    const uint32_t aoff = (uint32_t)((rb * 16 + (seg & 1) * 8 + lr) * SA + (seg >> 1) * 16);
    const uint32_t boff0 = (uint32_t)((chh * 32 + 0 * 16 + (seg >> 1) * 8 + lr) * SA + (seg & 1) * 16);
    const uint32_t boff1 = (uint32_t)((chh * 32 + 1 * 16 + (seg >> 1) * 8 + lr) * SA + (seg & 1) * 16);
    const uint32_t bhib = smb + B_HI;
    const uint32_t blob = smb + B_LO;

    const float blv = bl[h];
    float pool[4][2];
    #pragma unroll
    for (int nt = 0; nt < 4; ++nt) { pool[nt][0] = 0.f; pool[nt][1] = 0.f; }

    for (int t = 0; t < NTILES; ++t) {
        const int p = t & 1;
        // prefetch next tile into registers
        float4 fr[8];
        if (t + 1 < NTILES) {
            const int m0n = (t + 1) * TM;
            #pragma unroll
            for (int it = 0; it < 8; ++it) {
                int idx = tid + it * THREADS;
                int row = idx >> 5, c4 = idx & 31;
                fr[it] = *(const float4*)(kfp + (size_t)(m0n + row) * CDIM + c4 * 4);
            }
        }

        const uint32_t ahib = smb + (p ? A_HI1 : A_HI0);
        const uint32_t alob = smb + (p ? A_LO1 : A_LO0);

        float acc[4][4];
        #pragma unroll
        for (int nt = 0; nt < 4; ++nt)
            #pragma unroll
            for (int j = 0; j < 4; ++j) acc[nt][j] = 0.f;

        #pragma unroll
        for (int kc = 0; kc < 8; ++kc) {
            const uint32_t kb = kc * 32;
            uint32_t ah0, ah1, ah2, ah3, al0, al1, al2, al3;
            LDSM4(ah0, ah1, ah2, ah3, ahib + aoff + kb);
            LDSM4(al0, al1, al2, al3, alob + aoff + kb);
            uint32_t bh0, bh1, bh2, bh3, bl0, bl1, bl2, bl3;
            LDSM4(bh0, bh1, bh2, bh3, bhib + boff0 + kb);
            LDSM4(bl0, bl1, bl2, bl3, blob + boff0 + kb);
            mma16816(acc[0], ah0, ah1, ah2, ah3, bh0, bh1);
            mma16816(acc[1], ah0, ah1, ah2, ah3, bh2, bh3);
            mma16816(acc[0], al0, al1, al2, al3, bh0, bh1);
            mma16816(acc[1], al0, al1, al2, al3, bh2, bh3);
            mma16816(acc[0], ah0, ah1, ah2, ah3, bl0, bl1);
            mma16816(acc[1], ah0, ah1, ah2, ah3, bl2, bl3);
            LDSM4(bh0, bh1, bh2, bh3, bhib + boff1 + kb);
            LDSM4(bl0, bl1, bl2, bl3, blob + boff1 + kb);
            mma16816(acc[2], ah0, ah1, ah2, ah3, bh0, bh1);
            mma16816(acc[3], ah0, ah1, ah2, ah3, bh2, bh3);
            mma16816(acc[2], al0, al1, al2, al3, bh0, bh1);
            mma16816(acc[3], al0, al1, al2, al3, bh2, bh3);
            mma16816(acc[2], ah0, ah1, ah2, ah3, bl0, bl1);
            mma16816(acc[3], ah0, ah1, ah2, ah3, bl2, bl3);
        }

        // ---- epilogue in registers ----
        {
            const int r0 = lane >> 2;
            const int m0 = t * TM + rb * 16;
            const float mk0 = smask[m0 + r0];
            const float mk1 = smask[m0 + r0 + 8];
            float ls0 = 0.f, ls1 = 0.f;
            #pragma unroll
            for (int nt = 0; nt < 4; ++nt) {
                const int c = chh * 32 + nt * 8 + (lane & 3) * 2;
                const float b0 = sbb[c], b1 = sbb[c + 1];
                const float w0 = swl[c], w1 = swl[c + 1];
                float a00 = fmaxf(acc[nt][0] + b0, 0.f);
                float a01 = fmaxf(acc[nt][1] + b1, 0.f);
                float a10 = fmaxf(acc[nt][2] + b0, 0.f);
                float a11 = fmaxf(acc[nt][3] + b1, 0.f);
                pool[nt][0] = fmaf(a00, mk0, fmaf(a10, mk1, pool[nt][0]));
                pool[nt][1] = fmaf(a01, mk0, fmaf(a11, mk1, pool[nt][1]));
                ls0 = fmaf(a00, w0, fmaf(a01, w1, ls0));
                ls1 = fmaf(a10, w0, fmaf(a11, w1, ls1));
            }
            ls0 += __shfl_xor_sync(0xffffffffu, ls0, 1);
            ls0 += __shfl_xor_sync(0xffffffffu, ls0, 2);
            ls1 += __shfl_xor_sync(0xffffffffu, ls1, 1);
            ls1 += __shfl_xor_sync(0xffffffffu, ls1, 2);
            if ((lane & 3) == 0) {
                slgp[(rb * 16 + r0) * 2 + chh] = ls0;
                slgp[(rb * 16 + r0 + 8) * 2 + chh] = ls1;
            }
        }
        __syncthreads();
        if (tid < TM) {
            int m = t * TM + tid;
            float ls = slgp[tid * 2] + slgp[tid * 2 + 1];
            slg[m] = (smask[m] == 0.f) ? -1e9f : (ls + blv);
        }
        if (t + 1 < NTILES) {
            char* dh = smem + ((t + 1) & 1 ? A_HI1 : A_HI0);
            char* dl = smem + ((t + 1) & 1 ? A_LO1 : A_LO0);
            #pragma unroll
            for (int it = 0; it < 8; ++it) {
                int idx = tid + it * THREADS;
                int row = idx >> 5, c4 = idx & 31;
                uint2 hi, lo;
                cvt_hilo(fr[it], hi, lo);
                uint32_t off = (uint32_t)(row * SA + c4 * 8);
                *(uint2*)(dh + off) = hi;
                *(uint2*)(dl + off) = lo;
            }
        }
        __syncthreads();
    }

    // ---- pool: reduce over row-lanes, stage, combine over rowblocks ----
    #pragma unroll
    for (int nt = 0; nt < 4; ++nt)
        #pragma unroll
        for (int j = 0; j < 2; ++j) {
            float pv = pool[nt][j];
            pv += __shfl_xor_sync(0xffffffffu, pv, 4);
            pv += __shfl_xor_sync(0xffffffffu, pv, 8);
            pv += __shfl_xor_sync(0xffffffffu, pv, 16);
            if (lane < 4) ps[wid * 32 + nt * 8 + lane * 2 + j] = pv;
        }
    __syncthreads();
    if (tid < MIDD) {
        int o = tid, ch = o >> 5;
        float s = 0.f;
        #pragma unroll
        for (int r = 0; r < 8; ++r) s += ps[(ch * 8 + r) * 32 + (o & 31)];
        spool[o] = s;
    }
    if (tid == 0) {
        float c = 0.f;
        #pragma unroll
        for (int w = 0; w < 16; ++w) c += sred[1 + w];
        sred[0] = c;
    }
    __syncthreads();

    // ---- softmax over slg ----
    float lm = -3.0e38f;
    for (int m = tid; m < MDIM; m += THREADS) lm = fmaxf(lm, slg[m]);
    #pragma unroll
    for (int off = 16; off; off >>= 1) lm = fmaxf(lm, __shfl_xor_sync(0xffffffffu, lm, off));
    if (lane == 0) sred[17 + wid] = lm;
    __syncthreads();
    if (tid == 0) {
        float g = sred[17];
        #pragma unroll
        for (int w = 1; w < 16; ++w) g = fmaxf(g, sred[17 + w]);
        sred[33] = g;
    }
    __syncthreads();
    const float gmax = sred[33];
    float es = 0.f;
    for (int m = tid; m < MDIM; m += THREADS) {
        float e = expf(slg[m] - gmax);
        slg[m] = e;
        es += e;
    }
    #pragma unroll
    for (int off = 16; off; off >>= 1) es += __shfl_xor_sync(0xffffffffu, es, off);
    if (lane == 0) sred[34 + wid] = es;
    __syncthreads();
    if (tid == 0) {
        float s = 0.f;
        #pragma unroll
        for (int w = 0; w < 16; ++w) s += sred[34 + w];
        sred[50] = 1.f / s;
    }
    __syncthreads();
    const float inv = sred[50];
    for (int m = tid; m < MDIM; m += THREADS) slg[m] *= inv;
    __syncthreads();

    // ---- v2 = sum_m alpha[m]*value2[m,:]  (16 segs x 32 float4 chans), stage in A region ----
    float* vst = (float*)smem;
    {
        const int cb = (tid & 31) << 2;
        const int seg = tid >> 5;
        const float* vp = v2p + cb;
        float4 va = make_float4(0.f, 0.f, 0.f, 0.f);
        #pragma unroll 4
        for (int m = seg * 64; m < seg * 64 + 64; ++m) {
            float al = slg[m];
            float4 x = *(const float4*)(vp + (size_t)m * CDIM);
            va.x = fmaf(al, x.x, va.x);
            va.y = fmaf(al, x.y, va.y);
            va.z = fmaf(al, x.z, va.z);
            va.w = fmaf(al, x.w, va.w);
        }
        vst[seg * 128 + cb + 0] = va.x;
        vst[seg * 128 + cb + 1] = va.y;
        vst[seg * 128 + cb + 2] = va.z;
        vst[seg * 128 + cb + 3] = va.w;
    }
    __syncthreads();

    // ---- alpha_channel + final output ----
    if (tid < CDIM) {
        const int ch = tid;
        float v2c = 0.f;
        #pragma unroll
        for (int k = 0; k < 16; ++k) v2c += vst[k * 128 + ch];
        const float invc = 1.f / sred[0];
        float x = bl2[h * CDIM + ch];
        const float* w2 = wl2 + h * MIDD * CDIM + ch;
        #pragma unroll 8
        for (int o = 0; o < MIDD; ++o) x = fmaf(spool[o] * invc, w2[o * CDIM], x);
        float sig = 1.f / (1.f + expf(-x));
        out[bh * CDIM + ch] = v1[bh * CDIM + ch] * v2c * sig;
    }
}

extern "C" void kernel_launch(void* const* d_in, const int* in_sizes, int n_in,
                              void* d_out, int out_size) {
    const float* q   = (const float*)d_in[0];
    const float* kf  = (const float*)d_in[1];
    const int*   msk = (const int*)d_in[2];
    const float* v1  = (const float*)d_in[3];
    const float* v2  = (const float*)d_in[4];
    const float* wb  = (const float*)d_in[5];
    const float* bbp = (const float*)d_in[6];
    const float* wlp = (const float*)d_in[7];
    const float* blp = (const float*)d_in[8];
    const float* wl2 = (const float*)d_in[9];
    const float* bl2 = (const float*)d_in[10];
    float* out = (float*)d_out;

    cudaFuncSetAttribute(scatt_hmma, cudaFuncAttributeMaxDynamicSharedMemorySize, SMEM_TOTAL);
    scatt_hmma<<<512, THREADS, SMEM_TOTAL>>>(q, kf, msk, v1, v2, wb, bbp, wlp, blp, wl2, bl2, out);
}

// round 6
// speedup vs baseline: 2.2013x; 1.0406x over previous
#include <cuda_runtime.h>
#include <cuda_bf16.h>
#include <cstdint>

#define THREADS 512
#define MDIM 1024
#define CDIM 128
#define MIDD 64
#define TM 128
#define NTILES 8
#define SA 272                      /* row stride bytes (136 bf16) for A and B tiles */

// ---- smem byte offsets ----
#define A_HI0   0
#define A_HI1   34816
#define A_LO0   69632
#define A_LO1   104448
#define B_HI    139264
#define B_LO    156672
#define SMASK   174080              /* 1024 floats */
#define SLGT    178176              /* 128 floats: tile logits */
#define SP      178688              /* 128 floats: tile softmax weights */
#define SLGP    179200              /* 128 x 2 floats */
#define PST     180224              /* 16 x 128 floats: v2 warp partials */
#define PPOOL   188416              /* 16 x 32 floats: pool staging */
#define SPOOL   190464              /* 64 floats */
#define SBB     190720
#define SWL     190976
#define SRED    191232              /* 64 floats */
#define SMEM_TOTAL 191488

// sred slots: 0=mask count, 1..16 mask warp partials, 20..23 tile max partials,
// 28=M_new, 29=M_running, 30=scale, 32..47 lsum per warp, 48=inv_l

__device__ __forceinline__ uint32_t smem_u32(const void* p) {
    uint32_t a;
    asm("{ .reg .u64 t; cvta.to.shared.u64 t, %1; cvt.u32.u64 %0, t; }" : "=r"(a) : "l"(p));
    return a;
}
#define LDSM4(r0, r1, r2, r3, addr) \
    asm volatile("ldmatrix.sync.aligned.m8n8.x4.shared.b16 {%0,%1,%2,%3}, [%4];" \
                 : "=r"(r0), "=r"(r1), "=r"(r2), "=r"(r3) : "r"(addr))

__device__ __forceinline__ void mma16816(float* d, uint32_t a0, uint32_t a1, uint32_t a2, uint32_t a3,
                                         uint32_t b0, uint32_t b1) {
    asm volatile("mma.sync.aligned.m16n8k16.row.col.f32.bf16.bf16.f32 "
                 "{%0,%1,%2,%3}, {%4,%5,%6,%7}, {%8,%9}, {%0,%1,%2,%3};"
                 : "+f"(d[0]), "+f"(d[1]), "+f"(d[2]), "+f"(d[3])
                 : "r"(a0), "r"(a1), "r"(a2), "r"(a3), "r"(b0), "r"(b1));
}

__device__ __forceinline__ void cvt_hilo(float4 v, uint2& hi, uint2& lo) {
    __nv_bfloat162 h01 = __floats2bfloat162_rn(v.x, v.y);
    __nv_bfloat162 h23 = __floats2bfloat162_rn(v.z, v.w);
    float r0 = v.x - __bfloat162float(h01.x);
    float r1 = v.y - __bfloat162float(h01.y);
    float r2 = v.z - __bfloat162float(h23.x);
    float r3 = v.w - __bfloat162float(h23.y);
    __nv_bfloat162 l01 = __floats2bfloat162_rn(r0, r1);
    __nv_bfloat162 l23 = __floats2bfloat162_rn(r2, r3);
    hi = make_uint2(*(uint32_t*)&h01, *(uint32_t*)&h23);
    lo = make_uint2(*(uint32_t*)&l01, *(uint32_t*)&l23);
}

__global__ void __launch_bounds__(THREADS, 1) scatt_hmma(
    const float* __restrict__ q, const float* __restrict__ kf,
    const int* __restrict__ msk, const float* __restrict__ v1,
    const float* __restrict__ v2g, const float* __restrict__ wb,
    const float* __restrict__ bb, const float* __restrict__ wl,
    const float* __restrict__ bl, const float* __restrict__ wl2,
    const float* __restrict__ bl2, float* __restrict__ out)
{
    extern __shared__ char smem[];
    float* smask = (float*)(smem + SMASK);
    float* slgt  = (float*)(smem + SLGT);
    float* sp    = (float*)(smem + SP);
    float* slgp  = (float*)(smem + SLGP);
    float* pst   = (float*)(smem + PST);
    float* ppool = (float*)(smem + PPOOL);
    float* spool = (float*)(smem + SPOOL);
    float* sbb   = (float*)(smem + SBB);
    float* swl   = (float*)(smem + SWL);
    float* sred  = (float*)(smem + SRED);

    const int tid = threadIdx.x;
    const int wid = tid >> 5;
    const int lane = tid & 31;
    const int bh = blockIdx.x;
    const int b = bh >> 3;
    const int h = bh & 7;

    const float* qv  = q   + bh * CDIM;
    const float* kfp = kf  + (size_t)bh * MDIM * CDIM;
    const float* v2p = v2g + (size_t)bh * MDIM * CDIM;
    const float* wbh = wb  + h * CDIM * MIDD;
    const int*   mkp = msk + b * MDIM;

    const uint32_t smb = smem_u32(smem);

    if (tid == 0) sred[29] = -3.0e38f;

    // ---- build B hi/lo: qw[o][i] = q[i]*W[i][o], row=o (n), col=i (k), stride SA ----
    for (int idx = tid; idx < CDIM * MIDD; idx += THREADS) {
        int i = idx >> 6, o = idx & 63;
        float w = qv[i] * wbh[idx];
        __nv_bfloat16 hi = __float2bfloat16(w);
        __nv_bfloat16 lo = __float2bfloat16(w - __bfloat162float(hi));
        uint32_t off = (uint32_t)(o * SA + i * 2);
        *(__nv_bfloat16*)(smem + B_HI + off) = hi;
        *(__nv_bfloat16*)(smem + B_LO + off) = lo;
    }
    // ---- mask to smem + exact count (warp partials) ----
    {
        float cl = 0.f;
        for (int m = tid; m < MDIM; m += THREADS) {
            float mv = (float)mkp[m];
            smask[m] = mv;
            cl += mv;
        }
        #pragma unroll
        for (int off = 16; off; off >>= 1) cl += __shfl_xor_sync(0xffffffffu, cl, off);
        if (lane == 0) sred[1 + wid] = cl;
    }
    if (tid < MIDD) { sbb[tid] = bb[h * MIDD + tid]; swl[tid] = wl[h * MIDD + tid]; }

    // ---- preload tile 0 (convert + STS into buf 0) ----
    {
        #pragma unroll
        for (int it = 0; it < 8; ++it) {
            int idx = tid + it * THREADS;
            int row = idx >> 5, c4 = idx & 31;
            float4 v = *(const float4*)(kfp + (size_t)row * CDIM + c4 * 4);
            uint2 hi, lo;
            cvt_hilo(v, hi, lo);
            uint32_t off = (uint32_t)(row * SA + c4 * 8);
            *(uint2*)(smem + A_HI0 + off) = hi;
            *(uint2*)(smem + A_LO0 + off) = lo;
        }
    }
    __syncthreads();

    // ---- warp tiling ----
    const int rb = wid & 7;
    const int chh = wid >> 3;
    const int seg = lane >> 3;
    const int lr = lane & 7;
    const uint32_t aoff = (uint32_t)((rb * 16 + (seg & 1) * 8 + lr) * SA + (seg >> 1) * 16);
    const uint32_t boff0 = (uint32_t)((chh * 32 + (seg >> 1) * 8 + lr) * SA + (seg & 1) * 16);
    const uint32_t boff1 = (uint32_t)((chh * 32 + 16 + (seg >> 1) * 8 + lr) * SA + (seg & 1) * 16);
    const uint32_t bhib = smb + B_HI;
    const uint32_t blob = smb + B_LO;

    const float blv = bl[h];
    float pool[4][2];
    #pragma unroll
    for (int nt = 0; nt < 4; ++nt) { pool[nt][0] = 0.f; pool[nt][1] = 0.f; }
    float4 vacc = make_float4(0.f, 0.f, 0.f, 0.f);
    float lsum = 0.f;
    // v2 rows for this warp within each tile: wid*8 .. wid*8+7, channels lane*4..+4
    const float* v2w = v2p + (size_t)(wid * 8) * CDIM + (lane << 2);

    for (int t = 0; t < NTILES; ++t) {
        const int p = t & 1;
        // prefetch next A tile into registers
        float4 fr[8];
        if (t + 1 < NTILES) {
            const int m0n = (t + 1) * TM;
            #pragma unroll
            for (int it = 0; it < 8; ++it) {
                int idx = tid + it * THREADS;
                int row = idx >> 5, c4 = idx & 31;
                fr[it] = *(const float4*)(kfp + (size_t)(m0n + row) * CDIM + c4 * 4);
            }
        }
        // ---- pipelined v2 accumulation for tile t-1 (sp stable) ----
        if (t > 0) {
            const float* vr = v2w + (size_t)(t - 1) * TM * CDIM;
            #pragma unroll
            for (int r = 0; r < 8; ++r) {
                float pr = sp[wid * 8 + r];
                float4 x = *(const float4*)(vr + r * CDIM);
                vacc.x = fmaf(pr, x.x, vacc.x);
                vacc.y = fmaf(pr, x.y, vacc.y);
                vacc.z = fmaf(pr, x.z, vacc.z);
                vacc.w = fmaf(pr, x.w, vacc.w);
                lsum += pr;
            }
        }

        const uint32_t ahib = smb + (p ? A_HI1 : A_HI0);
        const uint32_t alob = smb + (p ? A_LO1 : A_LO0);

        float acc[4][4];
        #pragma unroll
        for (int nt = 0; nt < 4; ++nt)
            #pragma unroll
            for (int j = 0; j < 4; ++j) acc[nt][j] = 0.f;

        #pragma unroll
        for (int kc = 0; kc < 8; ++kc) {
            const uint32_t kb = kc * 32;
            uint32_t ah0, ah1, ah2, ah3, al0, al1, al2, al3;
            LDSM4(ah0, ah1, ah2, ah3, ahib + aoff + kb);
            LDSM4(al0, al1, al2, al3, alob + aoff + kb);
            uint32_t bh0, bh1, bh2, bh3, bl0, bl1, bl2, bl3;
            LDSM4(bh0, bh1, bh2, bh3, bhib + boff0 + kb);
            LDSM4(bl0, bl1, bl2, bl3, blob + boff0 + kb);
            mma16816(acc[0], ah0, ah1, ah2, ah3, bh0, bh1);
            mma16816(acc[1], ah0, ah1, ah2, ah3, bh2, bh3);
            mma16816(acc[0], al0, al1, al2, al3, bh0, bh1);
            mma16816(acc[1], al0, al1, al2, al3, bh2, bh3);
            mma16816(acc[0], ah0, ah1, ah2, ah3, bl0, bl1);
            mma16816(acc[1], ah0, ah1, ah2, ah3, bl2, bl3);
            LDSM4(bh0, bh1, bh2, bh3, bhib + boff1 + kb);
            LDSM4(bl0, bl1, bl2, bl3, blob + boff1 + kb);
            mma16816(acc[2], ah0, ah1, ah2, ah3, bh0, bh1);
            mma16816(acc[3], ah0, ah1, ah2, ah3, bh2, bh3);
            mma16816(acc[2], al0, al1, al2, al3, bh0, bh1);
            mma16816(acc[3], al0, al1, al2, al3, bh2, bh3);
            mma16816(acc[2], ah0, ah1, ah2, ah3, bl0, bl1);
            mma16816(acc[3], ah0, ah1, ah2, ah3, bl2, bl3);
        }

        // ---- epilogue in registers ----
        {
            const int r0 = lane >> 2;
            const int m0 = t * TM + rb * 16;
            const float mk0 = smask[m0 + r0];
            const float mk1 = smask[m0 + r0 + 8];
            float ls0 = 0.f, ls1 = 0.f;
            #pragma unroll
            for (int nt = 0; nt < 4; ++nt) {
                const int c = chh * 32 + nt * 8 + (lane & 3) * 2;
                const float b0 = sbb[c], b1 = sbb[c + 1];
                const float w0 = swl[c], w1 = swl[c + 1];
                float a00 = fmaxf(acc[nt][0] + b0, 0.f);
                float a01 = fmaxf(acc[nt][1] + b1, 0.f);
                float a10 = fmaxf(acc[nt][2] + b0, 0.f);
                float a11 = fmaxf(acc[nt][3] + b1, 0.f);
                pool[nt][0] = fmaf(a00, mk0, fmaf(a10, mk1, pool[nt][0]));
                pool[nt][1] = fmaf(a01, mk0, fmaf(a11, mk1, pool[nt][1]));
                ls0 = fmaf(a00, w0, fmaf(a01, w1, ls0));
                ls1 = fmaf(a10, w0, fmaf(a11, w1, ls1));
            }
            ls0 += __shfl_xor_sync(0xffffffffu, ls0, 1);
            ls0 += __shfl_xor_sync(0xffffffffu, ls0, 2);
            ls1 += __shfl_xor_sync(0xffffffffu, ls1, 1);
            ls1 += __shfl_xor_sync(0xffffffffu, ls1, 2);
            if ((lane & 3) == 0) {
                slgp[(rb * 16 + r0) * 2 + chh] = ls0;
                slgp[(rb * 16 + r0 + 8) * 2 + chh] = ls1;
            }
        }
        __syncthreads();                                   // sync1
        if (tid < TM) {
            int m = t * TM + tid;
            float ls = slgp[tid * 2] + slgp[tid * 2 + 1];
            float lg = (smask[m] == 0.f) ? -1e9f : (ls + blv);
            slgt[tid] = lg;
            float wm = lg;
            #pragma unroll
            for (int off = 16; off; off >>= 1) wm = fmaxf(wm, __shfl_xor_sync(0xffffffffu, wm, off));
            if (lane == 0) sred[20 + (tid >> 5)] = wm;
        }
        __syncthreads();                                   // sync2
        if (tid == 0) {
            float mn = fmaxf(fmaxf(sred[20], sred[21]), fmaxf(sred[22], sred[23]));
            float Mo = sred[29];
            float Mn = fmaxf(Mo, mn);
            sred[29] = Mn;
            sred[28] = Mn;
            sred[30] = expf(Mo - Mn);
        }
        __syncthreads();                                   // sync3
        {
            if (tid < TM) sp[tid] = expf(slgt[tid] - sred[28]);
            float sc = sred[30];
            vacc.x *= sc; vacc.y *= sc; vacc.z *= sc; vacc.w *= sc;
            lsum *= sc;
        }
        // STS prefetched A tile (frees fr before next iteration's v2 loads)
        if (t + 1 < NTILES) {
            char* dh = smem + ((t + 1) & 1 ? A_HI1 : A_HI0);
            char* dl = smem + ((t + 1) & 1 ? A_LO1 : A_LO0);
            #pragma unroll
            for (int it = 0; it < 8; ++it) {
                int idx = tid + it * THREADS;
                int row = idx >> 5, c4 = idx & 31;
                uint2 hi, lo;
                cvt_hilo(fr[it], hi, lo);
                uint32_t off = (uint32_t)(row * SA + c4 * 8);
                *(uint2*)(dh + off) = hi;
                *(uint2*)(dl + off) = lo;
            }
        }
        __syncthreads();                                   // sync4
    }

    // ---- drain: v2 accumulation for the last tile ----
    {
        const float* vr = v2w + (size_t)(NTILES - 1) * TM * CDIM;
        #pragma unroll
        for (int r = 0; r < 8; ++r) {
            float pr = sp[wid * 8 + r];
            float4 x = *(const float4*)(vr + r * CDIM);
            vacc.x = fmaf(pr, x.x, vacc.x);
            vacc.y = fmaf(pr, x.y, vacc.y);
            vacc.z = fmaf(pr, x.z, vacc.z);
            vacc.w = fmaf(pr, x.w, vacc.w);
            lsum += pr;
        }
    }

    // ---- stage v2 partials + lsum ----
    {
        float* d = pst + wid * 128 + (lane << 2);
        d[0] = vacc.x; d[1] = vacc.y; d[2] = vacc.z; d[3] = vacc.w;
        if (lane == 0) sred[32 + wid] = lsum;
    }
    // ---- pool: reduce over row-lanes, stage, combine over rowblocks ----
    #pragma unroll
    for (int nt = 0; nt < 4; ++nt)
        #pragma unroll
        for (int j = 0; j < 2; ++j) {
            float pv = pool[nt][j];
            pv += __shfl_xor_sync(0xffffffffu, pv, 4);
            pv += __shfl_xor_sync(0xffffffffu, pv, 8);
            pv += __shfl_xor_sync(0xffffffffu, pv, 16);
            if (lane < 4) ppool[wid * 32 + nt * 8 + lane * 2 + j] = pv;
        }
    __syncthreads();
    if (tid < MIDD) {
        int o = tid, ch = o >> 5;
        float s = 0.f;
        #pragma unroll
        for (int r = 0; r < 8; ++r) s += ppool[(ch * 8 + r) * 32 + (o & 31)];
        spool[o] = s;
    }
    if (tid == 0) {
        float c = 0.f;
        #pragma unroll
        for (int w = 0; w < 16; ++w) c += sred[1 + w];
        sred[0] = c;
        float l = 0.f;
        #pragma unroll
        for (int w = 0; w < 16; ++w) l += sred[32 + w];
        sred[48] = 1.f / l;
    }
    __syncthreads();

    // ---- alpha_channel + final output ----
    if (tid < CDIM) {
        const int ch = tid;
        float v2c = 0.f;
        #pragma unroll
        for (int w = 0; w < 16; ++w) v2c += pst[w * 128 + ch];
        v2c *= sred[48];
        const float invc = 1.f / sred[0];
        float x = bl2[h * CDIM + ch];
        const float* w2 = wl2 + h * MIDD * CDIM + ch;
        #pragma unroll 8
        for (int o = 0; o < MIDD; ++o) x = fmaf(spool[o] * invc, w2[o * CDIM], x);
        float sig = 1.f / (1.f + expf(-x));
        out[bh * CDIM + ch] = v1[bh * CDIM + ch] * v2c * sig;
    }
}

extern "C" void kernel_launch(void* const* d_in, const int* in_sizes, int n_in,
                              void* d_out, int out_size) {
    const float* q   = (const float*)d_in[0];
    const float* kf  = (const float*)d_in[1];
    const int*   msk = (const int*)d_in[2];
    const float* v1  = (const float*)d_in[3];
    const float* v2  = (const float*)d_in[4];
    const float* wb  = (const float*)d_in[5];
    const float* bbp = (const float*)d_in[6];
    const float* wlp = (const float*)d_in[7];
    const float* blp = (const float*)d_in[8];
    const float* wl2 = (const float*)d_in[9];
    const float* bl2 = (const float*)d_in[10];
    float* out = (float*)d_out;

    cudaFuncSetAttribute(scatt_hmma, cudaFuncAttributeMaxDynamicSharedMemorySize, SMEM_TOTAL);
    scatt_hmma<<<512, THREADS, SMEM_TOTAL>>>(q, kf, msk, v1, v2, wb, bbp, wlp, blp, wl2, bl2, out);
}